// round 10
// baseline (speedup 1.0000x reference)
#include <cuda_runtime.h>
#include <cstdint>

// ce_loss_aux: masked one-hot binary CE.
// Persistent deep-pipeline version: 592 persistent CTAs, DEPTH=4 ring of
// 8 KB slots (512 positions: 4 KB y_true + 4 KB y_pred) filled by
// cp.async.bulk. All smem static (32 KB + eps < 48 KB). Steady state keeps
// up to 32 KB per CTA in flight with zero register pressure; compute per
// stage is one FMA-select pair + one __logf per thread. Deterministic
// last-block final reduction.

#define NTHREADS    256
#define STAGE_POS   512
#define STAGE_PAIRS 256                          // float4 per array per stage
#define DEPTH       4
#define NBLOCKS     592                          // 148 SMs * 4

__device__ float        g_partials[1024];
__device__ unsigned int g_counter;               // zero-init; reset by last block

__device__ __forceinline__ uint32_t smem_u32(const void* p) {
    return (uint32_t)__cvta_generic_to_shared(p);
}

__device__ __forceinline__ void mbar_wait(uint32_t mbarA, uint32_t parity) {
    uint32_t done;
    asm volatile(
        "{\n\t.reg .pred p;\n\t"
        "mbarrier.try_wait.parity.acquire.cta.shared::cta.b64 p, [%1], %2;\n\t"
        "selp.b32 %0, 1, 0, p;\n\t}"
        : "=r"(done) : "r"(mbarA), "r"(parity) : "memory");
    if (!done) {
        asm volatile(
            "{\n\t.reg .pred P1;\n\t"
            "WAIT_LOOP_%=:\n\t"
            "mbarrier.try_wait.parity.acquire.cta.shared::cta.b64 P1, [%0], %1, 0x989680;\n\t"
            "@P1 bra.uni WAIT_DONE_%=;\n\t"
            "bra.uni WAIT_LOOP_%=;\n\t"
            "WAIT_DONE_%=:\n\t}"
            :: "r"(mbarA), "r"(parity) : "memory");
    }
}

__global__ __launch_bounds__(NTHREADS)
void ce_pipe_kernel(const float* __restrict__ y_true,
                    const float* __restrict__ y_pred,
                    const int*   __restrict__ doc_len,
                    float* __restrict__ out,
                    int B, int L, int chunkShift, int chunkMask,
                    int totalChunks, int nBlocks)
{
    __shared__ float4   sT[DEPTH][STAGE_PAIRS];   // 4 x 4 KB
    __shared__ float4   sP[DEPTH][STAGE_PAIRS];   // 4 x 4 KB
    __shared__ uint64_t mbar[DEPTH];

    const int tid = threadIdx.x;

    if (tid == 0) {
        #pragma unroll
        for (int s = 0; s < DEPTH; s++)
            asm volatile("mbarrier.init.shared.b64 [%0], 1;"
                         :: "r"(smem_u32(&mbar[s])) : "memory");
        asm volatile("fence.proxy.async.shared::cta;" ::: "memory");
    }
    __syncthreads();

    int prodIdx  = blockIdx.x;
    int issued   = 0, consumed = 0;
    int vsS[DEPTH];                               // per-slot valid count (uniform)
    float acc = 0.0f;

    for (;;) {
        // ---- fill: keep up to DEPTH stages outstanding ----
        while (issued - consumed < DEPTH) {
            int vs = 0;
            long long pb = 0;                     // float4 index of stage start
            while (prodIdx < totalChunks) {
                int c = prodIdx; prodIdx += nBlocks;
                int b     = c >> chunkShift;
                int chunk = c & chunkMask;
                int d     = __ldg(&doc_len[b]);
                int vv    = d - chunk * STAGE_POS;
                if (vv > 0) {
                    vs = vv < STAGE_POS ? vv : STAGE_POS;
                    pb = (long long)b * (L >> 1) + (long long)chunk * STAGE_PAIRS;
                    break;
                }
            }
            if (vs == 0) break;                   // nothing left to issue

            int slot = issued & (DEPTH - 1);
            vsS[slot] = vs;

            if (tid == 0) {
                uint32_t bytes = (uint32_t)((vs + 1) >> 1) * 16u;
                uint32_t mA = smem_u32(&mbar[slot]);
                const char* gT = (const char*)y_true + pb * 16;
                const char* gP = (const char*)y_pred + pb * 16;
                asm volatile("mbarrier.arrive.expect_tx.shared.b64 _, [%0], %1;"
                             :: "r"(mA), "r"(bytes * 2u) : "memory");
                asm volatile("cp.async.bulk.shared::cluster.global.mbarrier::complete_tx::bytes "
                             "[%0], [%1], %2, [%3];"
                             :: "r"(smem_u32(sT[slot])), "l"(gT), "r"(bytes), "r"(mA) : "memory");
                asm volatile("cp.async.bulk.shared::cluster.global.mbarrier::complete_tx::bytes "
                             "[%0], [%1], %2, [%3];"
                             :: "r"(smem_u32(sP[slot])), "l"(gP), "r"(bytes), "r"(mA) : "memory");
            }
            issued++;
        }
        if (consumed == issued) break;            // drained and no more work

        // ---- consume oldest stage ----
        int slot   = consumed & (DEPTH - 1);
        uint32_t parity = (uint32_t)(consumed / DEPTH) & 1u;
        mbar_wait(smem_u32(&mbar[slot]), parity);

        int vs = vsS[slot];
        float4 t = sT[slot][tid];
        float4 p = sP[slot][tid];
        int l0 = tid << 1;
        if (vs == STAGE_POS) {
            float s0 = t.x * p.x + t.y * p.y;     // one-hot select, exact
            float s1 = t.z * p.z + t.w * p.w;
            acc -= __logf(s0 * s1);               // product >= 1e-8: fp32 safe
        } else if (l0 < vs) {
            float s0 = t.x * p.x + t.y * p.y;
            float s1 = (l0 + 1 < vs) ? (t.z * p.z + t.w * p.w) : 1.0f;
            acc -= __logf(s0 * s1);
        }

        consumed++;
        __syncthreads();                          // all readers done before reuse
    }

    // ---- block reduction ----
    __shared__ float red[NTHREADS / 32];
    #pragma unroll
    for (int o = 16; o > 0; o >>= 1)
        acc += __shfl_down_sync(0xFFFFFFFFu, acc, o);
    if ((tid & 31) == 0) red[tid >> 5] = acc;
    __syncthreads();
    if (tid < 32) {
        float w = (tid < NTHREADS / 32) ? red[tid] : 0.0f;
        #pragma unroll
        for (int o = 4; o > 0; o >>= 1)
            w += __shfl_down_sync(0xFFFFFFFFu, w, o);
        if (tid == 0) g_partials[blockIdx.x] = w;
    }

    // ---- last-block final reduction (deterministic fixed-order sums) ----
    __shared__ bool amLast;
    if (tid == 0) {
        __threadfence();
        unsigned int prev = atomicAdd(&g_counter, 1u);
        amLast = (prev == (unsigned int)(nBlocks - 1));
    }
    __syncthreads();

    if (amLast) {
        float ls = 0.0f;
        for (int i = tid; i < nBlocks; i += NTHREADS)
            ls += g_partials[i];
        float ln = 0.0f;
        for (int i = tid; i < B; i += NTHREADS)
            ln += (float)__ldg(&doc_len[i]);

        #pragma unroll
        for (int o = 16; o > 0; o >>= 1) {
            ls += __shfl_down_sync(0xFFFFFFFFu, ls, o);
            ln += __shfl_down_sync(0xFFFFFFFFu, ln, o);
        }
        __shared__ float rl[NTHREADS / 32], rn[NTHREADS / 32];
        if ((tid & 31) == 0) { rl[tid >> 5] = ls; rn[tid >> 5] = ln; }
        __syncthreads();
        if (tid == 0) {
            float sumL = 0.0f, sumN = 0.0f;
            #pragma unroll
            for (int i = 0; i < NTHREADS / 32; i++) { sumL += rl[i]; sumN += rn[i]; }
            out[0] = sumL / sumN;
            g_counter = 0;                        // reset for next graph replay
        }
    }
}

extern "C" void kernel_launch(void* const* d_in, const int* in_sizes, int n_in,
                              void* d_out, int out_size)
{
    const float* y_true  = (const float*)d_in[0];
    const float* y_pred  = (const float*)d_in[1];
    const int*   doc_len = (const int*)d_in[2];
    float*       out     = (float*)d_out;

    int B = in_sizes[2];
    int L = in_sizes[0] / (2 * B);

    int chunksPerRow = L / STAGE_POS;             // 16 (power of two)
    int chunkShift = 0;
    while ((1 << chunkShift) < chunksPerRow) chunkShift++;
    int chunkMask  = chunksPerRow - 1;
    int totalChunks = B * chunksPerRow;
    int nBlocks = NBLOCKS < totalChunks ? NBLOCKS : totalChunks;

    ce_pipe_kernel<<<nBlocks, NTHREADS>>>(y_true, y_pred, doc_len, out,
                                          B, L, chunkShift, chunkMask,
                                          totalChunks, nBlocks);
}

// round 11
// speedup vs baseline: 1.4985x; 1.4985x over previous
#include <cuda_runtime.h>

// ce_loss_aux: masked one-hot binary CE.
// R3's winning geometry (1024 blocks x 256 threads, 2048 float4-pairs per
// block), with MUFU pressure cut 4x: one __logf per 4 float4-pairs
// (8 positions; product >= 1e-32, fp32-normal) and FMA-based one-hot
// selects (labels are exactly 0/1) instead of FSETP/FSEL chains.
// Deterministic last-block final reduction.

#define NTHREADS 256
#define PPT 8                                   // float4-pairs per thread
#define CHUNK_PAIRS (NTHREADS * PPT)            // 2048 pairs / block

__device__ float        g_partials[2048];
__device__ unsigned int g_counter;              // zero-init; reset by last block

__global__ __launch_bounds__(NTHREADS)
void ce_fused_kernel(const float* __restrict__ y_true,
                     const float* __restrict__ y_pred,
                     const int*   __restrict__ doc_len,
                     float* __restrict__ out,
                     int B, int L, int chunksPerRow, int nBlocks)
{
    const int tid   = threadIdx.x;
    const int b     = blockIdx.x / chunksPerRow;
    const int chunk = blockIdx.x - b * chunksPerRow;
    const int d     = __ldg(&doc_len[b]);

    const int pairBase = chunk * CHUNK_PAIRS;
    const int lStart   = pairBase * 2;

    float acc = 0.0f;

    if (lStart < d) {
        const float4* t4 = reinterpret_cast<const float4*>(y_true) + (size_t)b * (L >> 1);
        const float4* p4 = reinterpret_cast<const float4*>(y_pred) + (size_t)b * (L >> 1);

        if (lStart + CHUNK_PAIRS * 2 <= d) {
            // ---- fully valid: batched loads, 8-way product, 1 log / 4 pairs ----
            float4 t[PPT], p[PPT];
            #pragma unroll
            for (int i = 0; i < PPT; i++)
                t[i] = __ldg(&t4[pairBase + i * NTHREADS + tid]);
            #pragma unroll
            for (int i = 0; i < PPT; i++)
                p[i] = __ldg(&p4[pairBase + i * NTHREADS + tid]);

            #pragma unroll
            for (int j = 0; j < PPT / 4; j++) {
                float m = 1.0f;
                #pragma unroll
                for (int i = 4 * j; i < 4 * j + 4; i++) {
                    float s0 = t[i].x * p[i].x + t[i].y * p[i].y;  // exact one-hot select
                    float s1 = t[i].z * p[i].z + t[i].w * p[i].w;
                    m *= s0 * s1;                // 8 factors >= 1e-4 -> m >= 1e-32
                }
                acc -= __logf(m);
            }
        } else {
            // ---- boundary chunk: per-pair predication on d ----
            #pragma unroll
            for (int i = 0; i < PPT; i++) {
                int pr = pairBase + i * NTHREADS + tid;
                int l0 = pr << 1;
                if (l0 < d) {
                    float4 t = __ldg(&t4[pr]);
                    float4 p = __ldg(&p4[pr]);
                    float s0 = t.x * p.x + t.y * p.y;
                    float s1 = (l0 + 1 < d) ? (t.z * p.z + t.w * p.w) : 1.0f;
                    acc -= __logf(s0 * s1);
                }
            }
        }
    }

    // ---- block reduction ----
    __shared__ float red[NTHREADS / 32];
    #pragma unroll
    for (int o = 16; o > 0; o >>= 1)
        acc += __shfl_down_sync(0xFFFFFFFFu, acc, o);
    if ((tid & 31) == 0) red[tid >> 5] = acc;
    __syncthreads();
    if (tid < 32) {
        float w = (tid < NTHREADS / 32) ? red[tid] : 0.0f;
        #pragma unroll
        for (int o = 4; o > 0; o >>= 1)
            w += __shfl_down_sync(0xFFFFFFFFu, w, o);
        if (tid == 0) g_partials[blockIdx.x] = w;
    }

    // ---- last-block final reduction (deterministic fixed-order sums) ----
    __shared__ bool amLast;
    if (tid == 0) {
        __threadfence();
        unsigned int prev = atomicAdd(&g_counter, 1u);
        amLast = (prev == (unsigned int)(nBlocks - 1));
    }
    __syncthreads();

    if (amLast) {
        float ls = 0.0f;
        for (int i = tid; i < nBlocks; i += NTHREADS)
            ls += g_partials[i];
        float ln = 0.0f;
        for (int i = tid; i < B; i += NTHREADS)
            ln += (float)__ldg(&doc_len[i]);

        #pragma unroll
        for (int o = 16; o > 0; o >>= 1) {
            ls += __shfl_down_sync(0xFFFFFFFFu, ls, o);
            ln += __shfl_down_sync(0xFFFFFFFFu, ln, o);
        }
        __shared__ float rl[NTHREADS / 32], rn[NTHREADS / 32];
        if ((tid & 31) == 0) { rl[tid >> 5] = ls; rn[tid >> 5] = ln; }
        __syncthreads();
        if (tid == 0) {
            float sumL = 0.0f, sumN = 0.0f;
            #pragma unroll
            for (int i = 0; i < NTHREADS / 32; i++) { sumL += rl[i]; sumN += rn[i]; }
            out[0] = sumL / sumN;
            g_counter = 0;                      // reset for next graph replay
        }
    }
}

extern "C" void kernel_launch(void* const* d_in, const int* in_sizes, int n_in,
                              void* d_out, int out_size)
{
    const float* y_true  = (const float*)d_in[0];
    const float* y_pred  = (const float*)d_in[1];
    const int*   doc_len = (const int*)d_in[2];
    float*       out     = (float*)d_out;

    int B = in_sizes[2];
    int L = in_sizes[0] / (2 * B);

    int pairsPerRow  = L >> 1;
    int chunksPerRow = (pairsPerRow + CHUNK_PAIRS - 1) / CHUNK_PAIRS;
    int nBlocks      = B * chunksPerRow;

    ce_fused_kernel<<<nBlocks, NTHREADS>>>(y_true, y_pred, doc_len, out,
                                           B, L, chunksPerRow, nBlocks);
}

// round 12
// speedup vs baseline: 1.5343x; 1.0239x over previous
#include <cuda_runtime.h>

// ce_loss_aux: masked one-hot binary CE.
// R11 compute body (1024 blocks x 256 threads, 2048 float4-pairs per block,
// 8-way log-products, FMA one-hot selects) with the reduction tail replaced
// by deterministic fixed-point int64 atomics:
//   - each block atomicAdds round(partial * 2^20) to g_loss  (exact int add)
//   - chunk-0 blocks atomicAdd doc_len[b] to g_len
//   - last-arriving block computes out = g_loss / 2^20 / g_len and resets.

#define NTHREADS 256
#define PPT 8                                   // float4-pairs per thread
#define CHUNK_PAIRS (NTHREADS * PPT)            // 2048 pairs / block
#define FP_SCALE 1048576.0f                     // 2^20

__device__ unsigned long long g_loss;           // fixed-point loss sum
__device__ int                g_len;            // doc_len sum
__device__ unsigned int       g_counter;        // zero-init; reset by last block

__global__ __launch_bounds__(NTHREADS)
void ce_fused_kernel(const float* __restrict__ y_true,
                     const float* __restrict__ y_pred,
                     const int*   __restrict__ doc_len,
                     float* __restrict__ out,
                     int B, int L, int chunksPerRow, int nBlocks)
{
    const int tid   = threadIdx.x;
    const int b     = blockIdx.x / chunksPerRow;
    const int chunk = blockIdx.x - b * chunksPerRow;
    const int d     = __ldg(&doc_len[b]);

    const int pairBase = chunk * CHUNK_PAIRS;
    const int lStart   = pairBase * 2;

    float acc = 0.0f;

    if (lStart < d) {
        const float4* t4 = reinterpret_cast<const float4*>(y_true) + (size_t)b * (L >> 1);
        const float4* p4 = reinterpret_cast<const float4*>(y_pred) + (size_t)b * (L >> 1);

        if (lStart + CHUNK_PAIRS * 2 <= d) {
            // ---- fully valid: batched loads, 8-way product, 1 log / 4 pairs ----
            float4 t[PPT], p[PPT];
            #pragma unroll
            for (int i = 0; i < PPT; i++)
                t[i] = __ldg(&t4[pairBase + i * NTHREADS + tid]);
            #pragma unroll
            for (int i = 0; i < PPT; i++)
                p[i] = __ldg(&p4[pairBase + i * NTHREADS + tid]);

            #pragma unroll
            for (int j = 0; j < PPT / 4; j++) {
                float m = 1.0f;
                #pragma unroll
                for (int i = 4 * j; i < 4 * j + 4; i++) {
                    float s0 = t[i].x * p[i].x + t[i].y * p[i].y;  // exact one-hot select
                    float s1 = t[i].z * p[i].z + t[i].w * p[i].w;
                    m *= s0 * s1;                // 8 factors >= 1e-4 -> m >= 1e-32
                }
                acc -= __logf(m);
            }
        } else {
            // ---- boundary chunk: per-pair predication on d ----
            #pragma unroll
            for (int i = 0; i < PPT; i++) {
                int pr = pairBase + i * NTHREADS + tid;
                int l0 = pr << 1;
                if (l0 < d) {
                    float4 t = __ldg(&t4[pr]);
                    float4 p = __ldg(&p4[pr]);
                    float s0 = t.x * p.x + t.y * p.y;
                    float s1 = (l0 + 1 < d) ? (t.z * p.z + t.w * p.w) : 1.0f;
                    acc -= __logf(s0 * s1);
                }
            }
        }
    }

    // ---- block reduction ----
    __shared__ float red[NTHREADS / 32];
    #pragma unroll
    for (int o = 16; o > 0; o >>= 1)
        acc += __shfl_down_sync(0xFFFFFFFFu, acc, o);
    if ((tid & 31) == 0) red[tid >> 5] = acc;
    __syncthreads();

    // ---- atomic accumulation (exact integer adds -> deterministic) ----
    __shared__ bool amLast;
    if (tid == 0) {
        float v = 0.0f;
        #pragma unroll
        for (int i = 0; i < NTHREADS / 32; i++) v += red[i];
        unsigned long long q = (unsigned long long)__float2ll_rn(v * FP_SCALE);
        atomicAdd(&g_loss, q);
        if (chunk == 0) atomicAdd(&g_len, d);
        __threadfence();
        unsigned int prev = atomicAdd(&g_counter, 1u);
        amLast = (prev == (unsigned int)(nBlocks - 1));
    }
    __syncthreads();

    // ---- last block: finish from two scalars, reset for graph replay ----
    if (amLast && tid == 0) {
        unsigned long long ls = g_loss;
        int                ln = g_len;
        out[0] = (float)((double)ls / (double)FP_SCALE / (double)ln);
        g_loss    = 0ull;
        g_len     = 0;
        g_counter = 0;
    }
}

extern "C" void kernel_launch(void* const* d_in, const int* in_sizes, int n_in,
                              void* d_out, int out_size)
{
    const float* y_true  = (const float*)d_in[0];
    const float* y_pred  = (const float*)d_in[1];
    const int*   doc_len = (const int*)d_in[2];
    float*       out     = (float*)d_out;

    int B = in_sizes[2];
    int L = in_sizes[0] / (2 * B);

    int pairsPerRow  = L >> 1;
    int chunksPerRow = (pairsPerRow + CHUNK_PAIRS - 1) / CHUNK_PAIRS;
    int nBlocks      = B * chunksPerRow;

    ce_fused_kernel<<<nBlocks, NTHREADS>>>(y_true, y_pred, doc_len, out,
                                           B, L, chunksPerRow, nBlocks);
}